// round 8
// baseline (speedup 1.0000x reference)
#include <cuda_runtime.h>
#include <cuda_fp16.h>
#include <cstdint>

// ---------------------------------------------------------------------------
// out[m, c] = sum_f sin(2*pi*f*t[m])*As[c,f] + cos(2*pi*f*t[m])*Ac[c,f]
// GEMM: M = 262144, N = 256, K = 256 (K = [sin | cos] halves).
// mma.sync.m16n8k16 fp16->fp32. Persistent CTAs (1/SM), W fp16 in SMEM.
// R8: WARP SPECIALIZATION + frag pipelining.
//   320 threads: warps 0-7 = consumers (2M x 4N grid, 64x64 warp tiles =
//   traffic-optimal 4KB/row), warps 8-9 = producers (all sincos fill).
//   204-reg budget -> 128 acc regs fit with NO spills (R5 was capped at 255).
//   Consumers double-buffer A frags across k-steps and ping-pong B frags
//   within a k-step, so LDSM latency hides under the HMMA chain.
//   Single X buffer split by K-half (sin/cos) as in R5:
//     phase A: consumers MMA sin-half | producers fill cos-half (same tile)
//     phase B: consumers MMA cos-half | producers fill sin-half (next tile)
// ---------------------------------------------------------------------------

#define NT        320
#define NCONS     256               // consumer threads (8 warps)
#define MT        128
// SMEM layout (bytes):
//   W : 256 rows(c) x 256 k fp16, 512 B/row, XOR-swizzled -> 131072
//   X : 128 rows(m) x 256 k fp16, 512 B/row               ->  65536
//   F : 128 floats (freqs)                                ->    512
#define SW_OFF     0
#define SX_OFF     131072
#define SF_OFF     196608
#define SMEM_TOTAL 197120

static __device__ __forceinline__ uint32_t smem_u32(const void* p) {
    uint32_t a;
    asm("{ .reg .u64 t; cvta.to.shared.u64 t, %1; cvt.u32.u64 %0, t; }"
        : "=r"(a) : "l"(p));
    return a;
}

// byte offset of (row, 16B-chunk) in a 512 B/row tile with XOR swizzle:
// chunk' = chunk ^ (row & 7). Conflict-free for ldmatrix and the fills.
static __device__ __forceinline__ uint32_t swz(uint32_t row, uint32_t chunk) {
    return row * 512u + ((chunk ^ (row & 7u)) << 4);
}

#define LDSM_X4(r, addr) \
    asm volatile("ldmatrix.sync.aligned.m8n8.x4.shared.b16 {%0,%1,%2,%3}, [%4];" \
        : "=r"((r)[0]), "=r"((r)[1]), "=r"((r)[2]), "=r"((r)[3]) : "r"(addr))

#define MMA_16816(d, a, b0, b1) \
    asm volatile("mma.sync.aligned.m16n8k16.row.col.f32.f16.f16.f32 " \
        "{%0,%1,%2,%3}, {%4,%5,%6,%7}, {%8,%9}, {%0,%1,%2,%3};" \
        : "+f"((d)[0]), "+f"((d)[1]), "+f"((d)[2]), "+f"((d)[3]) \
        : "r"((a)[0]), "r"((a)[1]), "r"((a)[2]), "r"((a)[3]), \
          "r"(b0), "r"(b1))

// fill 4 freqs of sin (k=f) or cos (k=f+128) for one X row
template <bool USE_COS>
static __device__ __forceinline__ void fill_chunk4(char* xb, const float* sF,
                                                   float tv, int xrow, int f)
{
    const float4 fr = *reinterpret_cast<const float4*>(sF + f);
    float v0, v1, v2, v3, h, r, th;
    h = tv * fr.x; r = (h + 12582912.0f) - 12582912.0f;
    th = (h - r) * 6.283185307179586f; v0 = USE_COS ? __cosf(th) : __sinf(th);
    h = tv * fr.y; r = (h + 12582912.0f) - 12582912.0f;
    th = (h - r) * 6.283185307179586f; v1 = USE_COS ? __cosf(th) : __sinf(th);
    h = tv * fr.z; r = (h + 12582912.0f) - 12582912.0f;
    th = (h - r) * 6.283185307179586f; v2 = USE_COS ? __cosf(th) : __sinf(th);
    h = tv * fr.w; r = (h + 12582912.0f) - 12582912.0f;
    th = (h - r) * 6.283185307179586f; v3 = USE_COS ? __cosf(th) : __sinf(th);

    __half2 h0 = __floats2half2_rn(v0, v1);
    __half2 h1 = __floats2half2_rn(v2, v3);
    const uint32_t ch  = (uint32_t)(f >> 3) + (USE_COS ? 16u : 0u);
    const uint32_t off = ((uint32_t)(f >> 2) & 1u) << 3;   // 8B within chunk
    uint2 v;
    v.x = *reinterpret_cast<uint32_t*>(&h0);
    v.y = *reinterpret_cast<uint32_t*>(&h1);
    *reinterpret_cast<uint2*>(xb + swz((uint32_t)xrow, ch) + off) = v;
}

__global__ void __launch_bounds__(NT, 1)
fourier_mma_kernel(const float* __restrict__ t,
                   const float* __restrict__ freqs,
                   const float* __restrict__ As,
                   const float* __restrict__ Ac,
                   float* __restrict__ out,
                   int rows)
{
    extern __shared__ char smem[];
    char* sW  = smem + SW_OFF;
    char* sX  = smem + SX_OFF;
    float* sF = (float*)(smem + SF_OFF);
    const uint32_t uW = smem_u32(sW);
    const uint32_t uX = smem_u32(sX);

    const int tid  = threadIdx.x;
    const int lane = tid & 31;
    const int wid  = tid >> 5;
    const bool isProd = (tid >= NCONS);

    // ---- one-time: freqs + W fp32->fp16 into swizzled SMEM ----------------
    if (tid < 128) sF[tid] = freqs[tid];
    for (int i = tid; i < 256 * 64; i += NT) {
        const int n  = i >> 6;
        const int j4 = i & 63;
        const int k0 = j4 << 2;
        const float* src = (k0 < 128) ? (As + n * 128 + k0)
                                      : (Ac + n * 128 + (k0 - 128));
        const float4 w = *reinterpret_cast<const float4*>(src);
        __half2 h0 = __floats2half2_rn(w.x, w.y);
        __half2 h1 = __floats2half2_rn(w.z, w.w);
        uint32_t byte = swz((uint32_t)n, (uint32_t)(j4 >> 1)) + ((uint32_t)(j4 & 1) << 3);
        uint2 v;
        v.x = *reinterpret_cast<uint32_t*>(&h0);
        v.y = *reinterpret_cast<uint32_t*>(&h1);
        *reinterpret_cast<uint2*>(sW + byte) = v;
    }

    // ---- producer constants: 64 threads, 2/row-slot, 4 rows each ----------
    const int ptid = tid - NCONS;              // 0..63 when producer
    const int prow = (ptid >> 1) & 31;         // base row 0..31 (+32k below)
    const int pf0  = (ptid & 1) << 6;          // 64 freqs per thread

    // ---- consumer constants: warp grid 2 (M) x 4 (N), tile 64x64 ----------
    const int wm = wid >> 2;
    const int wn = wid & 3;
    const int gid = lane >> 2, tig = lane & 3;
    const int aRow0   = wm * 64 + (lane & 15);
    const int aHi     = lane >> 4;
    const int bRowOff = (lane & 7) + ((lane >> 4) << 3);
    const int bHi     = (lane >> 3) & 1;

    const int numTiles = rows / MT;            // 2048
    const int stride   = gridDim.x;
    int tile = blockIdx.x;
    if (tile >= numTiles) return;

    __syncthreads();                           // W + freqs visible

    // ---- prologue: producers fill sin half of first tile ------------------
    if (isProd) {
        #pragma unroll
        for (int r = 0; r < 4; r++) {
            const int row = prow + r * 32;
            const float tv = t[tile * MT + row];
            #pragma unroll 4
            for (int j = 0; j < 16; j++)
                fill_chunk4<false>(sX, sF, tv, row, pf0 + j * 4);
        }
    }
    __syncthreads();

    for (; tile < numTiles; tile += stride) {
        const int  nextTile = tile + stride;
        const bool hasNext  = nextTile < numTiles;
        const int m0 = tile * MT;

        if (!isProd) {
            // ================= CONSUMER: pure LDSM + MMA =====================
            float acc[4][8][4];
            #pragma unroll
            for (int mi = 0; mi < 4; mi++)
                #pragma unroll
                for (int ni = 0; ni < 8; ni++)
                    #pragma unroll
                    for (int q = 0; q < 4; q++) acc[mi][ni][q] = 0.0f;

            #pragma unroll
            for (int ph = 0; ph < 2; ph++) {
                const int ksBase = ph * 8;
                uint32_t a[2][4][4];                 // A frags, dbl-buffered
                #pragma unroll
                for (int mi = 0; mi < 4; mi++) {
                    const uint32_t row = (uint32_t)(aRow0 + mi * 16);
                    LDSM_X4(a[0][mi], uX + swz(row, (uint32_t)(ksBase * 2 + aHi)));
                }
                #pragma unroll
                for (int kk = 0; kk < 8; kk++) {
                    const int ks  = ksBase + kk;
                    const int cur = kk & 1;
                    uint32_t bq[2][4];
                    LDSM_X4(bq[0], uW + swz((uint32_t)(wn * 64 + bRowOff),
                                            (uint32_t)(ks * 2 + bHi)));
                    if (kk < 7) {                    // prefetch next A frags
                        #pragma unroll
                        for (int mi = 0; mi < 4; mi++) {
                            const uint32_t row = (uint32_t)(aRow0 + mi * 16);
                            LDSM_X4(a[cur ^ 1][mi],
                                    uX + swz(row, (uint32_t)((ks + 1) * 2 + aHi)));
                        }
                    }
                    #pragma unroll
                    for (int nt = 0; nt < 4; nt++) {
                        if (nt < 3) {                // prefetch next B frag
                            const uint32_t n =
                                (uint32_t)(wn * 64 + (nt + 1) * 16 + bRowOff);
                            LDSM_X4(bq[(nt + 1) & 1],
                                    uW + swz(n, (uint32_t)(ks * 2 + bHi)));
                        }
                        const uint32_t* bb = bq[nt & 1];
                        #pragma unroll
                        for (int mi = 0; mi < 4; mi++) {
                            MMA_16816(acc[mi][nt * 2],     a[cur][mi], bb[0], bb[1]);
                            MMA_16816(acc[mi][nt * 2 + 1], a[cur][mi], bb[2], bb[3]);
                        }
                    }
                }
                __syncthreads();   // end of phase: other half ready / freed
            }

            // ---- epilogue: regs -> gmem (STG.64) ---------------------------
            #pragma unroll
            for (int mi = 0; mi < 4; mi++) {
                const size_t mrow = (size_t)(m0 + wm * 64 + mi * 16 + gid);
                float* o0 = out + mrow * 256 + wn * 64 + tig * 2;
                #pragma unroll
                for (int ni = 0; ni < 8; ni++) {
                    float2 v0, v1;
                    v0.x = acc[mi][ni][0]; v0.y = acc[mi][ni][1];
                    v1.x = acc[mi][ni][2]; v1.y = acc[mi][ni][3];
                    *reinterpret_cast<float2*>(o0 + ni * 8)        = v0;  // row m
                    *reinterpret_cast<float2*>(o0 + ni * 8 + 2048) = v1;  // row m+8
                }
            }
        } else {
            // ================= PRODUCER: sincos fill =========================
            // phase A: fill cos half of THIS tile
            #pragma unroll
            for (int r = 0; r < 4; r++) {
                const int row = prow + r * 32;
                const float tv = t[m0 + row];
                #pragma unroll 4
                for (int j = 0; j < 16; j++)
                    fill_chunk4<true>(sX, sF, tv, row, pf0 + j * 4);
            }
            __syncthreads();       // cos half ready; sin half now free
            // phase B: fill sin half of NEXT tile
            if (hasNext) {
                #pragma unroll
                for (int r = 0; r < 4; r++) {
                    const int row = prow + r * 32;
                    const float tv = t[nextTile * MT + row];
                    #pragma unroll 4
                    for (int j = 0; j < 16; j++)
                        fill_chunk4<false>(sX, sF, tv, row, pf0 + j * 4);
                }
            }
            __syncthreads();       // sin half of next tile ready
        }
    }
}

extern "C" void kernel_launch(void* const* d_in, const int* in_sizes, int n_in,
                              void* d_out, int out_size)
{
    const float* t     = (const float*)d_in[0];
    const float* freqs = (const float*)d_in[1];
    const float* As    = (const float*)d_in[2];
    const float* Ac    = (const float*)d_in[3];
    float* out         = (float*)d_out;

    int sm_count = 148;
    cudaDeviceGetAttribute(&sm_count, cudaDevAttrMultiProcessorCount, 0);
    cudaFuncSetAttribute(fourier_mma_kernel,
                         cudaFuncAttributeMaxDynamicSharedMemorySize, SMEM_TOTAL);

    const int rows = in_sizes[0];          // B*L = 262144
    fourier_mma_kernel<<<sm_count, NT, SMEM_TOTAL>>>(t, freqs, As, Ac, out, rows);
}

// round 9
// speedup vs baseline: 1.6094x; 1.6094x over previous
#include <cuda_runtime.h>
#include <cuda_fp16.h>
#include <cstdint>

// ---------------------------------------------------------------------------
// out[m, c] = sum_f sin(2*pi*f*t[m])*As[c,f] + cos(2*pi*f*t[m])*Ac[c,f]
// GEMM: M = 262144, N = 256, K = 256 (K = [sin | cos] halves).
// R9: A-OPERAND COMPUTED IN REGISTERS (no X SMEM, no fill, no A-ldmatrix,
// no barriers in the main loop). Each lane synthesizes its m16n8k16 A
// fragment per the PTX layout: rows {gid, gid+8}, cols {2t,2t+1,2t+8,2t+9}
// -> 4x4 outer product theta = t_row * (2pi f_col), sin for k<128 half,
// cos for k>=128 half. B (W matrix) stays fp16 in SMEM via ldmatrix.
// 256 threads, warp grid 2(M) x 4(N), warp tile 32x64, persistent CTAs.
// ---------------------------------------------------------------------------

#define NT        256
#define MT        64                     // rows per CTA iteration
#define SMEM_TOTAL 131072                // W only: 256 x 256 fp16

static __device__ __forceinline__ uint32_t smem_u32(const void* p) {
    uint32_t a;
    asm("{ .reg .u64 t; cvta.to.shared.u64 t, %1; cvt.u32.u64 %0, t; }"
        : "=r"(a) : "l"(p));
    return a;
}

// byte offset of (row, 16B-chunk) in a 512 B/row tile with XOR swizzle:
// chunk' = chunk ^ (row & 7). Conflict-free for ldmatrix and the fills.
static __device__ __forceinline__ uint32_t swz(uint32_t row, uint32_t chunk) {
    return row * 512u + ((chunk ^ (row & 7u)) << 4);
}

#define LDSM_X4(r, addr) \
    asm volatile("ldmatrix.sync.aligned.m8n8.x4.shared.b16 {%0,%1,%2,%3}, [%4];" \
        : "=r"((r)[0]), "=r"((r)[1]), "=r"((r)[2]), "=r"((r)[3]) : "r"(addr))

#define MMA_16816(d, a, b0, b1) \
    asm volatile("mma.sync.aligned.m16n8k16.row.col.f32.f16.f16.f32 " \
        "{%0,%1,%2,%3}, {%4,%5,%6,%7}, {%8,%9}, {%0,%1,%2,%3};" \
        : "+f"((d)[0]), "+f"((d)[1]), "+f"((d)[2]), "+f"((d)[3]) \
        : "r"((a)[0]), "r"((a)[1]), "r"((a)[2]), "r"((a)[3]), \
          "r"(b0), "r"(b1))

static __device__ __forceinline__ uint32_t packh2(float x, float y) {
    __half2 h = __floats2half2_rn(x, y);
    return *reinterpret_cast<uint32_t*>(&h);
}

__global__ void __launch_bounds__(NT, 1)
fourier_mma_kernel(const float* __restrict__ t,
                   const float* __restrict__ freqs,
                   const float* __restrict__ As,
                   const float* __restrict__ Ac,
                   float* __restrict__ out,
                   int rows)
{
    extern __shared__ char smem[];
    char* sW = smem;
    const uint32_t uW = smem_u32(sW);

    const int tid  = threadIdx.x;
    const int lane = tid & 31;
    const int wid  = tid >> 5;

    // ---- one-time: W fp32->fp16 into swizzled SMEM ------------------------
    for (int i = tid; i < 256 * 64; i += NT) {
        const int n  = i >> 6;
        const int j4 = i & 63;
        const int k0 = j4 << 2;
        const float* src = (k0 < 128) ? (As + n * 128 + k0)
                                      : (Ac + n * 128 + (k0 - 128));
        const float4 w = *reinterpret_cast<const float4*>(src);
        uint32_t byte = swz((uint32_t)n, (uint32_t)(j4 >> 1)) + ((uint32_t)(j4 & 1) << 3);
        uint2 v;
        v.x = packh2(w.x, w.y);
        v.y = packh2(w.z, w.w);
        *reinterpret_cast<uint2*>(sW + byte) = v;
    }

    // ---- consumer constants: warp grid 2 (M) x 4 (N), tile 32x64 ----------
    const int wm  = wid >> 2;
    const int wn  = wid & 3;
    const int gid = lane >> 2, tig = lane & 3;
    const int bRowOff = (lane & 7) + ((lane >> 4) << 3);
    const int bHi     = (lane >> 3) & 1;

    // ---- preload this lane's 32 frequencies (x 2pi) into registers --------
    // k-step ks (0..7) uses freq cols {16ks + 2tig + {0,1,8,9}}
    float F2[32];
    #pragma unroll
    for (int j = 0; j < 32; j++) {
        const int ks = j >> 2, d = j & 3;
        const int col = ks * 16 + tig * 2 + (d & 1) + ((d & 2) << 2);
        F2[j] = freqs[col] * 6.283185307179586f;
    }

    const int numTiles = rows / MT;        // 4096
    const int stride   = gridDim.x;

    __syncthreads();                       // W visible to all warps

    for (int tile = blockIdx.x; tile < numTiles; tile += stride) {
        const int m0 = tile * MT;
        const int rbase = m0 + wm * 32 + gid;
        // t values for this lane's 4 fragment rows
        float tv0 = t[rbase];
        float tv1 = t[rbase + 8];
        float tv2 = t[rbase + 16];
        float tv3 = t[rbase + 24];

        float acc[2][8][4];
        #pragma unroll
        for (int mi = 0; mi < 2; mi++)
            #pragma unroll
            for (int ni = 0; ni < 8; ni++)
                #pragma unroll
                for (int q = 0; q < 4; q++) acc[mi][ni][q] = 0.0f;

        #pragma unroll
        for (int ks = 0; ks < 16; ks++) {
            const int kf = ks & 7;
            // ---- B fragments first (longest latency) ----------------------
            uint32_t b[4][4];
            #pragma unroll
            for (int nt = 0; nt < 4; nt++) {
                const uint32_t n = (uint32_t)(wn * 64 + nt * 16 + bRowOff);
                LDSM_X4(b[nt], uW + swz(n, (uint32_t)(ks * 2 + bHi)));
            }

            // ---- synthesize A fragments: 4 rows x 4 freq cols -------------
            const float Fa = F2[kf * 4 + 0], Fb = F2[kf * 4 + 1];
            const float Fc = F2[kf * 4 + 2], Fd = F2[kf * 4 + 3];
            float s[4][4];
            if (ks < 8) {
                s[0][0] = __sinf(tv0 * Fa); s[0][1] = __sinf(tv0 * Fb);
                s[0][2] = __sinf(tv0 * Fc); s[0][3] = __sinf(tv0 * Fd);
                s[1][0] = __sinf(tv1 * Fa); s[1][1] = __sinf(tv1 * Fb);
                s[1][2] = __sinf(tv1 * Fc); s[1][3] = __sinf(tv1 * Fd);
                s[2][0] = __sinf(tv2 * Fa); s[2][1] = __sinf(tv2 * Fb);
                s[2][2] = __sinf(tv2 * Fc); s[2][3] = __sinf(tv2 * Fd);
                s[3][0] = __sinf(tv3 * Fa); s[3][1] = __sinf(tv3 * Fb);
                s[3][2] = __sinf(tv3 * Fc); s[3][3] = __sinf(tv3 * Fd);
            } else {
                s[0][0] = __cosf(tv0 * Fa); s[0][1] = __cosf(tv0 * Fb);
                s[0][2] = __cosf(tv0 * Fc); s[0][3] = __cosf(tv0 * Fd);
                s[1][0] = __cosf(tv1 * Fa); s[1][1] = __cosf(tv1 * Fb);
                s[1][2] = __cosf(tv1 * Fc); s[1][3] = __cosf(tv1 * Fd);
                s[2][0] = __cosf(tv2 * Fa); s[2][1] = __cosf(tv2 * Fb);
                s[2][2] = __cosf(tv2 * Fc); s[2][3] = __cosf(tv2 * Fd);
                s[3][0] = __cosf(tv3 * Fa); s[3][1] = __cosf(tv3 * Fb);
                s[3][2] = __cosf(tv3 * Fc); s[3][3] = __cosf(tv3 * Fd);
            }
            // PTX m16n8k16 A layout: a0=(r,c01) a1=(r+8,c01) a2=(r,c89) a3=(r+8,c89)
            uint32_t a[2][4];
            #pragma unroll
            for (int mi = 0; mi < 2; mi++) {
                a[mi][0] = packh2(s[mi * 2][0],     s[mi * 2][1]);
                a[mi][1] = packh2(s[mi * 2 + 1][0], s[mi * 2 + 1][1]);
                a[mi][2] = packh2(s[mi * 2][2],     s[mi * 2][3]);
                a[mi][3] = packh2(s[mi * 2 + 1][2], s[mi * 2 + 1][3]);
            }

            // ---- MMA ------------------------------------------------------
            #pragma unroll
            for (int nt = 0; nt < 4; nt++) {
                const uint32_t* bb = b[nt];
                #pragma unroll
                for (int mi = 0; mi < 2; mi++) {
                    MMA_16816(acc[mi][nt * 2],     a[mi], bb[0], bb[1]);
                    MMA_16816(acc[mi][nt * 2 + 1], a[mi], bb[2], bb[3]);
                }
            }
        }

        // ---- epilogue: regs -> gmem (STG.64) ------------------------------
        #pragma unroll
        for (int mi = 0; mi < 2; mi++) {
            const size_t mrow = (size_t)(rbase + mi * 16);
            float* o0 = out + mrow * 256 + wn * 64 + tig * 2;
            #pragma unroll
            for (int ni = 0; ni < 8; ni++) {
                float2 v0, v1;
                v0.x = acc[mi][ni][0]; v0.y = acc[mi][ni][1];
                v1.x = acc[mi][ni][2]; v1.y = acc[mi][ni][3];
                *reinterpret_cast<float2*>(o0 + ni * 8)        = v0;  // row r
                *reinterpret_cast<float2*>(o0 + ni * 8 + 2048) = v1;  // row r+8
            }
        }
    }
}

extern "C" void kernel_launch(void* const* d_in, const int* in_sizes, int n_in,
                              void* d_out, int out_size)
{
    const float* t     = (const float*)d_in[0];
    const float* freqs = (const float*)d_in[1];
    const float* As    = (const float*)d_in[2];
    const float* Ac    = (const float*)d_in[3];
    float* out         = (float*)d_out;

    int sm_count = 148;
    cudaDeviceGetAttribute(&sm_count, cudaDevAttrMultiProcessorCount, 0);
    cudaFuncSetAttribute(fourier_mma_kernel,
                         cudaFuncAttributeMaxDynamicSharedMemorySize, SMEM_TOTAL);

    const int rows = in_sizes[0];          // B*L = 262144
    fourier_mma_kernel<<<sm_count, NT, SMEM_TOTAL>>>(t, freqs, As, Ac, out, rows);
}